// round 2
// baseline (speedup 1.0000x reference)
#include <cuda_runtime.h>

#define NN   20000
#define INCH 256
#define HEADS 8
#define HID  32
#define C1   256      // HEADS*HID
#define OUTC 40
#define E0   320000
#define ET   340000   // + self loops
#define NEG  0.2f
#define ENC_NEG_INF 0x007FFFFFu

// ---------------- scratch (device globals; no allocation allowed) ----------
__device__ float    g_h1[NN * C1];        // x @ W1
__device__ float    g_as1[NN * HEADS];
__device__ float    g_ad1[NN * HEADS];
__device__ float    g_e1[ET * HEADS];     // edge logits -> exp values
__device__ unsigned g_m1[NN * HEADS];     // encoded float max
__device__ float    g_den1[NN * HEADS];
__device__ float    g_out1[NN * C1];      // layer1 aggregate -> elu(h)
__device__ float    g_h2[NN * OUTC];      // h @ W2
__device__ float    g_as2[NN];
__device__ float    g_ad2[NN];
__device__ float    g_e2[ET];
__device__ unsigned g_m2[NN];
__device__ float    g_den2[NN];
__device__ float    g_out2[NN * OUTC];

// ---------------- helpers ---------------------------------------------------
__device__ __forceinline__ unsigned encf(float f) {
    unsigned u = __float_as_uint(f);
    return (u & 0x80000000u) ? ~u : (u | 0x80000000u);
}
__device__ __forceinline__ float decf(unsigned e) {
    return (e & 0x80000000u) ? __uint_as_float(e ^ 0x80000000u)
                             : __uint_as_float(~e);
}
__device__ __forceinline__ void red_add_v4(float* addr, float a, float b, float c, float d) {
    asm volatile("red.global.add.v4.f32 [%0], {%1, %2, %3, %4};"
                 :: "l"(addr), "f"(a), "f"(b), "f"(c), "f"(d) : "memory");
}

// ---------------- init (reset accumulators each replay) --------------------
__global__ void init_kernel() {
    int i = blockIdx.x * blockDim.x + threadIdx.x;
    int stride = gridDim.x * blockDim.x;
    for (int j = i; j < NN * C1; j += stride)   g_out1[j] = 0.f;
    for (int j = i; j < NN * OUTC; j += stride) g_out2[j] = 0.f;
    for (int j = i; j < NN * HEADS; j += stride) { g_m1[j] = ENC_NEG_INF; g_den1[j] = 0.f; }
    for (int j = i; j < NN; j += stride)         { g_m2[j] = ENC_NEG_INF; g_den2[j] = 0.f; }
}

// ---------------- generic tiled SGEMM (row-major A,B,C) --------------------
template<int BM, int BN, int BK, int TM, int TN>
__device__ __forceinline__ void sgemm_body(const float* __restrict__ A,
                                           const float* __restrict__ B,
                                           float* __restrict__ C,
                                           int M, int N, int K) {
    constexpr int TX = BN / TN;
    constexpr int TY = BM / TM;
    constexpr int NT = TX * TY;
    __shared__ float As[BK][BM + 1];
    __shared__ float Bs[BK][BN];
    int tx = threadIdx.x, ty = threadIdx.y;
    int tid = ty * TX + tx;
    int m0 = blockIdx.y * BM, n0 = blockIdx.x * BN;

    float acc[TM][TN];
#pragma unroll
    for (int i = 0; i < TM; i++)
#pragma unroll
        for (int j = 0; j < TN; j++) acc[i][j] = 0.f;

    for (int k0 = 0; k0 < K; k0 += BK) {
        for (int idx = tid; idx < BM * BK; idx += NT) {
            int m = idx / BK, k = idx % BK;
            int gm = m0 + m;
            As[k][m] = (gm < M) ? A[(size_t)gm * K + k0 + k] : 0.f;
        }
        for (int idx = tid; idx < BK * BN; idx += NT) {
            int k = idx / BN, n = idx % BN;
            int gn = n0 + n;
            Bs[k][n] = (gn < N) ? B[(size_t)(k0 + k) * N + gn] : 0.f;
        }
        __syncthreads();
#pragma unroll
        for (int k = 0; k < BK; k++) {
            float ra[TM], rb[TN];
#pragma unroll
            for (int i = 0; i < TM; i++) ra[i] = As[k][ty * TM + i];
#pragma unroll
            for (int j = 0; j < TN; j++) rb[j] = Bs[k][tx * TN + j];
#pragma unroll
            for (int i = 0; i < TM; i++)
#pragma unroll
                for (int j = 0; j < TN; j++) acc[i][j] += ra[i] * rb[j];
        }
        __syncthreads();
    }
#pragma unroll
    for (int i = 0; i < TM; i++) {
        int gm = m0 + ty * TM + i;
        if (gm >= M) continue;
#pragma unroll
        for (int j = 0; j < TN; j++) {
            int gn = n0 + tx * TN + j;
            if (gn < N) C[(size_t)gm * N + gn] = acc[i][j];
        }
    }
}

__global__ void gemm1_kernel(const float* __restrict__ x, const float* __restrict__ W1) {
    sgemm_body<64, 64, 16, 4, 4>(x, W1, g_h1, NN, C1, INCH);
}
__global__ void gemm2_kernel(const float* __restrict__ W2) {
    sgemm_body<64, 40, 16, 4, 4>(g_out1, W2, g_h2, NN, OUTC, C1);
}

// ---------------- alpha projections -----------------------------------------
// block = 256 threads = 8 warps, one node per block; warp w handles head w.
__global__ void alpha1_kernel(const float* __restrict__ a_src, const float* __restrict__ a_dst) {
    int n = blockIdx.x;
    int t = threadIdx.x;
    int h = t >> 5, l = t & 31;
    float v = g_h1[n * C1 + t];
    float s = v * a_src[t];
    float d = v * a_dst[t];
#pragma unroll
    for (int o = 16; o; o >>= 1) {
        s += __shfl_xor_sync(~0u, s, o);
        d += __shfl_xor_sync(~0u, d, o);
    }
    if (l == 0) { g_as1[n * HEADS + h] = s; g_ad1[n * HEADS + h] = d; }
}

// warp per node, 40 channels
__global__ void alpha2_kernel(const float* __restrict__ a_src, const float* __restrict__ a_dst) {
    int w = (blockIdx.x * blockDim.x + threadIdx.x) >> 5;
    int l = threadIdx.x & 31;
    if (w >= NN) return;
    float v = g_h2[w * OUTC + l];
    float s = v * a_src[l];
    float d = v * a_dst[l];
    if (l < OUTC - 32) {
        float v2 = g_h2[w * OUTC + 32 + l];
        s += v2 * a_src[32 + l];
        d += v2 * a_dst[32 + l];
    }
#pragma unroll
    for (int o = 16; o; o >>= 1) {
        s += __shfl_xor_sync(~0u, s, o);
        d += __shfl_xor_sync(~0u, d, o);
    }
    if (l == 0) { g_as2[w] = s; g_ad2[w] = d; }
}

// ---------------- layer1 edge passes ----------------------------------------
// edge_index is int32 on device (JAX x64 disabled downcasts int64 -> int32)
__global__ void edge_max1(const int* __restrict__ ei) {
    int i = blockIdx.x * blockDim.x + threadIdx.x;
    if (i >= ET * HEADS) return;
    int e = i >> 3, h = i & 7;
    int s, d;
    if (e < E0) { s = ei[e]; d = ei[E0 + e]; } else { s = d = e - E0; }
    float v = g_as1[s * HEADS + h] + g_ad1[d * HEADS + h];
    v = v > 0.f ? v : NEG * v;
    g_e1[i] = v;
    atomicMax(&g_m1[d * HEADS + h], encf(v));
}

__global__ void edge_sum1(const int* __restrict__ ei) {
    int i = blockIdx.x * blockDim.x + threadIdx.x;
    if (i >= ET * HEADS) return;
    int e = i >> 3, h = i & 7;
    int d = (e < E0) ? ei[E0 + e] : (e - E0);
    float m = decf(g_m1[d * HEADS + h]);
    float ex = __expf(g_e1[i] - m);
    g_e1[i] = ex;
    atomicAdd(&g_den1[d * HEADS + h], ex);
}

// warp per edge; two iterations of 32 lanes x float4 cover 256 channels
__global__ void edge_aggr1(const int* __restrict__ ei) {
    int w = (blockIdx.x * blockDim.x + threadIdx.x) >> 5;
    int l = threadIdx.x & 31;
    if (w >= ET) return;
    int s, d;
    if (w < E0) { s = ei[w]; d = ei[E0 + w]; } else { s = d = w - E0; }
#pragma unroll
    for (int p = 0; p < 2; p++) {
        int ch = p * 128 + l * 4;
        int h = ch >> 5;
        float ex  = g_e1[w * HEADS + h];
        float den = g_den1[d * HEADS + h];
        float al  = ex / (den + 1e-16f);
        float4 hv = *reinterpret_cast<const float4*>(&g_h1[s * C1 + ch]);
        red_add_v4(&g_out1[d * C1 + ch], hv.x * al, hv.y * al, hv.z * al, hv.w * al);
    }
}

__global__ void bias_elu(const float* __restrict__ b1) {
    int i = blockIdx.x * blockDim.x + threadIdx.x;
    if (i >= NN * C1) return;
    float v = g_out1[i] + b1[i & (C1 - 1)];
    g_out1[i] = v > 0.f ? v : expm1f(v);
}

// ---------------- layer2 edge passes ----------------------------------------
__global__ void edge_max2(const int* __restrict__ ei) {
    int e = blockIdx.x * blockDim.x + threadIdx.x;
    if (e >= ET) return;
    int s, d;
    if (e < E0) { s = ei[e]; d = ei[E0 + e]; } else { s = d = e - E0; }
    float v = g_as2[s] + g_ad2[d];
    v = v > 0.f ? v : NEG * v;
    g_e2[e] = v;
    atomicMax(&g_m2[d], encf(v));
}

__global__ void edge_sum2(const int* __restrict__ ei) {
    int e = blockIdx.x * blockDim.x + threadIdx.x;
    if (e >= ET) return;
    int d = (e < E0) ? ei[E0 + e] : (e - E0);
    float m = decf(g_m2[d]);
    float ex = __expf(g_e2[e] - m);
    g_e2[e] = ex;
    atomicAdd(&g_den2[d], ex);
}

// warp per edge; lanes 0..9 handle 40 channels via float4
__global__ void edge_aggr2(const int* __restrict__ ei) {
    int w = (blockIdx.x * blockDim.x + threadIdx.x) >> 5;
    int l = threadIdx.x & 31;
    if (w >= ET) return;
    int s, d;
    if (w < E0) { s = ei[w]; d = ei[E0 + w]; } else { s = d = w - E0; }
    if (l < OUTC / 4) {
        float al = g_e2[w] / (g_den2[d] + 1e-16f);
        float4 hv = *reinterpret_cast<const float4*>(&g_h2[s * OUTC + l * 4]);
        red_add_v4(&g_out2[d * OUTC + l * 4], hv.x * al, hv.y * al, hv.z * al, hv.w * al);
    }
}

// ---------------- log_softmax ------------------------------------------------
__global__ void lsm_kernel(const float* __restrict__ b2, float* __restrict__ out) {
    int w = (blockIdx.x * blockDim.x + threadIdx.x) >> 5;
    int l = threadIdx.x & 31;
    if (w >= NN) return;
    float v1 = g_out2[w * OUTC + l] + b2[l];
    float v2 = (l < 8) ? (g_out2[w * OUTC + 32 + l] + b2[32 + l]) : -1e30f;
    float m = fmaxf(v1, v2);
#pragma unroll
    for (int o = 16; o; o >>= 1) m = fmaxf(m, __shfl_xor_sync(~0u, m, o));
    float sum = __expf(v1 - m) + ((l < 8) ? __expf(v2 - m) : 0.f);
#pragma unroll
    for (int o = 16; o; o >>= 1) sum += __shfl_xor_sync(~0u, sum, o);
    float lse = m + logf(sum);
    out[w * OUTC + l] = v1 - lse;
    if (l < 8) out[w * OUTC + 32 + l] = v2 - lse;
}

// ---------------- launch ------------------------------------------------------
extern "C" void kernel_launch(void* const* d_in, const int* in_sizes, int n_in,
                              void* d_out, int out_size) {
    const float* x   = (const float*)d_in[0];
    const int*   ei  = (const int*)d_in[1];
    const float* W1  = (const float*)d_in[2];
    const float* a1s = (const float*)d_in[3];
    const float* a1d = (const float*)d_in[4];
    const float* b1  = (const float*)d_in[5];
    const float* W2  = (const float*)d_in[6];
    const float* a2s = (const float*)d_in[7];
    const float* a2d = (const float*)d_in[8];
    const float* b2  = (const float*)d_in[9];
    float*       out = (float*)d_out;

    init_kernel<<<4096, 256>>>();

    gemm1_kernel<<<dim3(C1 / 64, (NN + 63) / 64), dim3(16, 16)>>>(x, W1);
    alpha1_kernel<<<NN, 256>>>(a1s, a1d);

    int eth = ET * HEADS;
    edge_max1<<<(eth + 255) / 256, 256>>>(ei);
    edge_sum1<<<(eth + 255) / 256, 256>>>(ei);
    edge_aggr1<<<(ET + 7) / 8, 256>>>(ei);

    bias_elu<<<(NN * C1 + 255) / 256, 256>>>(b1);

    gemm2_kernel<<<dim3(1, (NN + 63) / 64), dim3(10, 16)>>>(W2);
    alpha2_kernel<<<(NN + 7) / 8, 256>>>(a2s, a2d);

    edge_max2<<<(ET + 255) / 256, 256>>>(ei);
    edge_sum2<<<(ET + 255) / 256, 256>>>(ei);
    edge_aggr2<<<(ET + 7) / 8, 256>>>(ei);

    lsm_kernel<<<(NN + 7) / 8, 256>>>(b2, out);
}

// round 3
// speedup vs baseline: 1.0159x; 1.0159x over previous
#include <cuda_runtime.h>

#define NN   20000
#define INCH 256
#define HEADS 8
#define HID  32
#define C1   256      // HEADS*HID
#define OUTC 40
#define E0   320000
#define ET   340000   // + self loops
#define NEG  0.2f
#define ENC_NEG_INF 0x007FFFFFu

// ---------------- scratch (device globals; no allocation allowed) ----------
__device__ float    g_h1[NN * C1];        // x @ W1
__device__ float    g_as1[NN * HEADS];
__device__ float    g_ad1[NN * HEADS];
__device__ float    g_e1[ET * HEADS];     // edge logits -> exp values
__device__ unsigned g_m1[NN * HEADS];     // encoded float max
__device__ float    g_den1[NN * HEADS];
__device__ float    g_out1[NN * C1];      // layer1 aggregate -> elu(h)
__device__ float    g_h2[NN * OUTC];      // h @ W2
__device__ float    g_as2[NN];
__device__ float    g_ad2[NN];
__device__ float    g_e2[ET];
__device__ unsigned g_m2[NN];
__device__ float    g_den2[NN];
__device__ float    g_out2[NN * OUTC];

// ---------------- helpers ---------------------------------------------------
__device__ __forceinline__ unsigned encf(float f) {
    unsigned u = __float_as_uint(f);
    return (u & 0x80000000u) ? ~u : (u | 0x80000000u);
}
__device__ __forceinline__ float decf(unsigned e) {
    return (e & 0x80000000u) ? __uint_as_float(e ^ 0x80000000u)
                             : __uint_as_float(~e);
}
__device__ __forceinline__ void red_add_v4(float* addr, float a, float b, float c, float d) {
    asm volatile("red.global.add.v4.f32 [%0], {%1, %2, %3, %4};"
                 :: "l"(addr), "f"(a), "f"(b), "f"(c), "f"(d) : "memory");
}

// ---------------- init (reset accumulators each replay) --------------------
__global__ void init_kernel() {
    int i = blockIdx.x * blockDim.x + threadIdx.x;
    int stride = gridDim.x * blockDim.x;
    for (int j = i; j < NN * C1; j += stride)   g_out1[j] = 0.f;
    for (int j = i; j < NN * OUTC; j += stride) g_out2[j] = 0.f;
    for (int j = i; j < NN * HEADS; j += stride) { g_m1[j] = ENC_NEG_INF; g_den1[j] = 0.f; }
    for (int j = i; j < NN; j += stride)         { g_m2[j] = ENC_NEG_INF; g_den2[j] = 0.f; }
}

// ---------------- generic tiled SGEMM (row-major A,B,C) --------------------
template<int BM, int BN, int BK, int TM, int TN>
__device__ __forceinline__ void sgemm_body(const float* __restrict__ A,
                                           const float* __restrict__ B,
                                           float* __restrict__ C,
                                           int M, int N, int K) {
    constexpr int TX = BN / TN;
    constexpr int TY = BM / TM;
    constexpr int NT = TX * TY;
    __shared__ float As[BK][BM + 1];
    __shared__ float Bs[BK][BN];
    int tx = threadIdx.x, ty = threadIdx.y;
    int tid = ty * TX + tx;
    int m0 = blockIdx.y * BM, n0 = blockIdx.x * BN;

    float acc[TM][TN];
#pragma unroll
    for (int i = 0; i < TM; i++)
#pragma unroll
        for (int j = 0; j < TN; j++) acc[i][j] = 0.f;

    for (int k0 = 0; k0 < K; k0 += BK) {
        for (int idx = tid; idx < BM * BK; idx += NT) {
            int m = idx / BK, k = idx % BK;
            int gm = m0 + m;
            As[k][m] = (gm < M) ? A[(size_t)gm * K + k0 + k] : 0.f;
        }
        for (int idx = tid; idx < BK * BN; idx += NT) {
            int k = idx / BN, n = idx % BN;
            int gn = n0 + n;
            Bs[k][n] = (gn < N) ? B[(size_t)(k0 + k) * N + gn] : 0.f;
        }
        __syncthreads();
#pragma unroll
        for (int k = 0; k < BK; k++) {
            float ra[TM], rb[TN];
#pragma unroll
            for (int i = 0; i < TM; i++) ra[i] = As[k][ty * TM + i];
#pragma unroll
            for (int j = 0; j < TN; j++) rb[j] = Bs[k][tx * TN + j];
#pragma unroll
            for (int i = 0; i < TM; i++)
#pragma unroll
                for (int j = 0; j < TN; j++) acc[i][j] += ra[i] * rb[j];
        }
        __syncthreads();
    }
#pragma unroll
    for (int i = 0; i < TM; i++) {
        int gm = m0 + ty * TM + i;
        if (gm >= M) continue;
#pragma unroll
        for (int j = 0; j < TN; j++) {
            int gn = n0 + tx * TN + j;
            if (gn < N) C[(size_t)gm * N + gn] = acc[i][j];
        }
    }
}

__global__ void gemm1_kernel(const float* __restrict__ x, const float* __restrict__ W1) {
    sgemm_body<64, 64, 16, 4, 4>(x, W1, g_h1, NN, C1, INCH);
}
__global__ void gemm2_kernel(const float* __restrict__ W2) {
    sgemm_body<64, 40, 16, 4, 4>(g_out1, W2, g_h2, NN, OUTC, C1);
}

// ---------------- alpha projections -----------------------------------------
// block = 256 threads = 8 warps, one node per block; warp w handles head w.
__global__ void alpha1_kernel(const float* __restrict__ a_src, const float* __restrict__ a_dst) {
    int n = blockIdx.x;
    int t = threadIdx.x;
    int h = t >> 5, l = t & 31;
    float v = g_h1[n * C1 + t];
    float s = v * a_src[t];
    float d = v * a_dst[t];
#pragma unroll
    for (int o = 16; o; o >>= 1) {
        s += __shfl_xor_sync(~0u, s, o);
        d += __shfl_xor_sync(~0u, d, o);
    }
    if (l == 0) { g_as1[n * HEADS + h] = s; g_ad1[n * HEADS + h] = d; }
}

// warp per node, 40 channels
__global__ void alpha2_kernel(const float* __restrict__ a_src, const float* __restrict__ a_dst) {
    int w = (blockIdx.x * blockDim.x + threadIdx.x) >> 5;
    int l = threadIdx.x & 31;
    if (w >= NN) return;
    float v = g_h2[w * OUTC + l];
    float s = v * a_src[l];
    float d = v * a_dst[l];
    if (l < OUTC - 32) {
        float v2 = g_h2[w * OUTC + 32 + l];
        s += v2 * a_src[32 + l];
        d += v2 * a_dst[32 + l];
    }
#pragma unroll
    for (int o = 16; o; o >>= 1) {
        s += __shfl_xor_sync(~0u, s, o);
        d += __shfl_xor_sync(~0u, d, o);
    }
    if (l == 0) { g_as2[w] = s; g_ad2[w] = d; }
}

// ---------------- layer1 edge passes ----------------------------------------
// edge_index is int32 on device (JAX x64 disabled downcasts int64 -> int32)
__global__ void edge_max1(const int* __restrict__ ei) {
    int i = blockIdx.x * blockDim.x + threadIdx.x;
    if (i >= ET * HEADS) return;
    int e = i >> 3, h = i & 7;
    int s, d;
    if (e < E0) { s = ei[e]; d = ei[E0 + e]; } else { s = d = e - E0; }
    float v = g_as1[s * HEADS + h] + g_ad1[d * HEADS + h];
    v = v > 0.f ? v : NEG * v;
    g_e1[i] = v;
    atomicMax(&g_m1[d * HEADS + h], encf(v));
}

__global__ void edge_sum1(const int* __restrict__ ei) {
    int i = blockIdx.x * blockDim.x + threadIdx.x;
    if (i >= ET * HEADS) return;
    int e = i >> 3, h = i & 7;
    int d = (e < E0) ? ei[E0 + e] : (e - E0);
    float m = decf(g_m1[d * HEADS + h]);
    float ex = __expf(g_e1[i] - m);
    g_e1[i] = ex;
    atomicAdd(&g_den1[d * HEADS + h], ex);
}

// warp per edge; two iterations of 32 lanes x float4 cover 256 channels
__global__ void edge_aggr1(const int* __restrict__ ei) {
    int w = (blockIdx.x * blockDim.x + threadIdx.x) >> 5;
    int l = threadIdx.x & 31;
    if (w >= ET) return;
    int s, d;
    if (w < E0) { s = ei[w]; d = ei[E0 + w]; } else { s = d = w - E0; }
#pragma unroll
    for (int p = 0; p < 2; p++) {
        int ch = p * 128 + l * 4;
        int h = ch >> 5;
        float ex  = g_e1[w * HEADS + h];
        float den = g_den1[d * HEADS + h];
        float al  = ex / (den + 1e-16f);
        float4 hv = *reinterpret_cast<const float4*>(&g_h1[s * C1 + ch]);
        red_add_v4(&g_out1[d * C1 + ch], hv.x * al, hv.y * al, hv.z * al, hv.w * al);
    }
}

__global__ void bias_elu(const float* __restrict__ b1) {
    int i = blockIdx.x * blockDim.x + threadIdx.x;
    if (i >= NN * C1) return;
    float v = g_out1[i] + b1[i & (C1 - 1)];
    g_out1[i] = v > 0.f ? v : expm1f(v);
}

// ---------------- layer2 edge passes ----------------------------------------
__global__ void edge_max2(const int* __restrict__ ei) {
    int e = blockIdx.x * blockDim.x + threadIdx.x;
    if (e >= ET) return;
    int s, d;
    if (e < E0) { s = ei[e]; d = ei[E0 + e]; } else { s = d = e - E0; }
    float v = g_as2[s] + g_ad2[d];
    v = v > 0.f ? v : NEG * v;
    g_e2[e] = v;
    atomicMax(&g_m2[d], encf(v));
}

__global__ void edge_sum2(const int* __restrict__ ei) {
    int e = blockIdx.x * blockDim.x + threadIdx.x;
    if (e >= ET) return;
    int d = (e < E0) ? ei[E0 + e] : (e - E0);
    float m = decf(g_m2[d]);
    float ex = __expf(g_e2[e] - m);
    g_e2[e] = ex;
    atomicAdd(&g_den2[d], ex);
}

// warp per edge; lanes 0..9 handle 40 channels via float4
__global__ void edge_aggr2(const int* __restrict__ ei) {
    int w = (blockIdx.x * blockDim.x + threadIdx.x) >> 5;
    int l = threadIdx.x & 31;
    if (w >= ET) return;
    int s, d;
    if (w < E0) { s = ei[w]; d = ei[E0 + w]; } else { s = d = w - E0; }
    if (l < OUTC / 4) {
        float al = g_e2[w] / (g_den2[d] + 1e-16f);
        float4 hv = *reinterpret_cast<const float4*>(&g_h2[s * OUTC + l * 4]);
        red_add_v4(&g_out2[d * OUTC + l * 4], hv.x * al, hv.y * al, hv.z * al, hv.w * al);
    }
}

// ---------------- log_softmax ------------------------------------------------
__global__ void lsm_kernel(const float* __restrict__ b2, float* __restrict__ out) {
    int w = (blockIdx.x * blockDim.x + threadIdx.x) >> 5;
    int l = threadIdx.x & 31;
    if (w >= NN) return;
    float v1 = g_out2[w * OUTC + l] + b2[l];
    float v2 = (l < 8) ? (g_out2[w * OUTC + 32 + l] + b2[32 + l]) : -1e30f;
    float m = fmaxf(v1, v2);
#pragma unroll
    for (int o = 16; o; o >>= 1) m = fmaxf(m, __shfl_xor_sync(~0u, m, o));
    float sum = __expf(v1 - m) + ((l < 8) ? __expf(v2 - m) : 0.f);
#pragma unroll
    for (int o = 16; o; o >>= 1) sum += __shfl_xor_sync(~0u, sum, o);
    float lse = m + logf(sum);
    out[w * OUTC + l] = v1 - lse;
    if (l < 8) out[w * OUTC + 32 + l] = v2 - lse;
}

// ---------------- launch ------------------------------------------------------
extern "C" void kernel_launch(void* const* d_in, const int* in_sizes, int n_in,
                              void* d_out, int out_size) {
    const float* x   = (const float*)d_in[0];
    const int*   ei  = (const int*)d_in[1];
    const float* W1  = (const float*)d_in[2];
    const float* a1s = (const float*)d_in[3];
    const float* a1d = (const float*)d_in[4];
    const float* b1  = (const float*)d_in[5];
    const float* W2  = (const float*)d_in[6];
    const float* a2s = (const float*)d_in[7];
    const float* a2d = (const float*)d_in[8];
    const float* b2  = (const float*)d_in[9];
    float*       out = (float*)d_out;

    init_kernel<<<4096, 256>>>();

    gemm1_kernel<<<dim3(C1 / 64, (NN + 63) / 64), dim3(16, 16)>>>(x, W1);
    alpha1_kernel<<<NN, 256>>>(a1s, a1d);

    int eth = ET * HEADS;
    edge_max1<<<(eth + 255) / 256, 256>>>(ei);
    edge_sum1<<<(eth + 255) / 256, 256>>>(ei);
    edge_aggr1<<<(ET + 7) / 8, 256>>>(ei);

    bias_elu<<<(NN * C1 + 255) / 256, 256>>>(b1);

    gemm2_kernel<<<dim3(1, (NN + 63) / 64), dim3(10, 16)>>>(W2);
    alpha2_kernel<<<(NN + 7) / 8, 256>>>(a2s, a2d);

    edge_max2<<<(ET + 255) / 256, 256>>>(ei);
    edge_sum2<<<(ET + 255) / 256, 256>>>(ei);
    edge_aggr2<<<(ET + 7) / 8, 256>>>(ei);

    lsm_kernel<<<(NN + 7) / 8, 256>>>(b2, out);
}

// round 4
// speedup vs baseline: 1.5528x; 1.5285x over previous
#include <cuda_runtime.h>

#define NN   20000
#define INCH 256
#define HEADS 8
#define HID  32
#define C1   256      // HEADS*HID
#define OUTC 40
#define E0   320000
#define ET   340000   // + self loops
#define NEG  0.2f

// ---------------- scratch (device globals; no allocation allowed) ----------
__device__ float g_h1[NN * C1];        // x @ W1
__device__ float g_as1[NN * HEADS];
__device__ float g_ad1[NN * HEADS];
__device__ float g_e1[ET * HEADS];     // exp(edge logits)
__device__ float g_den1[NN * HEADS];
__device__ float g_out1[NN * C1];      // layer1 aggregate (pre-bias/elu)
__device__ float g_h2[NN * OUTC];      // elu(out1+b1) @ W2
__device__ float g_as2[NN];
__device__ float g_ad2[NN];
__device__ float g_e2[ET];
__device__ float g_den2[NN];
__device__ float g_out2[NN * OUTC];

// ---------------- helpers ---------------------------------------------------
__device__ __forceinline__ void red_add_v4(float* addr, float a, float b, float c, float d) {
    asm volatile("red.global.add.v4.f32 [%0], {%1, %2, %3, %4};"
                 :: "l"(addr), "f"(a), "f"(b), "f"(c), "f"(d) : "memory");
}
__device__ __forceinline__ unsigned f2tf32(float f) {
    unsigned r;
    asm volatile("cvt.rna.tf32.f32 %0, %1;" : "=r"(r) : "f"(f));
    return r;
}
__device__ __forceinline__ void mma_tf32(float* c, const unsigned* a, unsigned b0, unsigned b1) {
    asm volatile(
        "mma.sync.aligned.m16n8k8.row.col.f32.tf32.tf32.f32 "
        "{%0,%1,%2,%3}, {%4,%5,%6,%7}, {%8,%9}, {%0,%1,%2,%3};"
        : "+f"(c[0]), "+f"(c[1]), "+f"(c[2]), "+f"(c[3])
        : "r"(a[0]), "r"(a[1]), "r"(a[2]), "r"(a[3]), "r"(b0), "r"(b1));
}

// ---------------- init (reset accumulators each replay) --------------------
__global__ void init_kernel() {
    int i = blockIdx.x * blockDim.x + threadIdx.x;
    int stride = gridDim.x * blockDim.x;
    for (int j = i; j < NN * C1; j += stride)    g_out1[j] = 0.f;
    for (int j = i; j < NN * OUTC; j += stride)  g_out2[j] = 0.f;
    for (int j = i; j < NN * HEADS; j += stride) g_den1[j] = 0.f;
    for (int j = i; j < NN; j += stride)         g_den2[j] = 0.f;
}

// ---------------- GEMM1: h1 = x @ W1  (tf32 tensor cores) -------------------
// block tile 128x128, 8 warps (4 m x 2 n), warp tile 32x64, K staged 32.
__global__ __launch_bounds__(256) void gemm1_kernel(const float* __restrict__ x,
                                                    const float* __restrict__ W1) {
    __shared__ float As[128][36];   // [m][k], stride 36 -> conflict-free frags
    __shared__ float Bs[32][136];   // [k][n], stride 136 -> conflict-free frags
    int tid = threadIdx.x;
    int lane = tid & 31, wid = tid >> 5;
    int wm = wid & 3, wn = wid >> 2;
    int g = lane >> 2, tg = lane & 3;
    int m0 = blockIdx.y * 128, n0 = blockIdx.x * 128;

    float acc[2][8][4];
#pragma unroll
    for (int i = 0; i < 2; i++)
#pragma unroll
        for (int j = 0; j < 8; j++)
#pragma unroll
            for (int k = 0; k < 4; k++) acc[i][j][k] = 0.f;

    int a_r = tid >> 3;            // 0..31
    int a_c = (tid & 7) * 4;       // 0..28
    int b_r = tid >> 3;            // 0..31
    int b_c0 = tid & 7;            // 0..7 (x4 stages of 8 float4)

    for (int k0 = 0; k0 < INCH; k0 += 32) {
        // load A tile 128x32 (rows guarded)
#pragma unroll
        for (int j = 0; j < 4; j++) {
            int r = a_r + 32 * j;
            int gm = m0 + r;
            float4 v = make_float4(0.f, 0.f, 0.f, 0.f);
            if (gm < NN) v = *reinterpret_cast<const float4*>(&x[(size_t)gm * INCH + k0 + a_c]);
            As[r][a_c + 0] = __uint_as_float(f2tf32(v.x));
            As[r][a_c + 1] = __uint_as_float(f2tf32(v.y));
            As[r][a_c + 2] = __uint_as_float(f2tf32(v.z));
            As[r][a_c + 3] = __uint_as_float(f2tf32(v.w));
        }
        // load B tile 32x128
#pragma unroll
        for (int j = 0; j < 4; j++) {
            int c = (b_c0 + 8 * j) * 4;
            float4 v = *reinterpret_cast<const float4*>(&W1[(size_t)(k0 + b_r) * C1 + n0 + c]);
            Bs[b_r][c + 0] = __uint_as_float(f2tf32(v.x));
            Bs[b_r][c + 1] = __uint_as_float(f2tf32(v.y));
            Bs[b_r][c + 2] = __uint_as_float(f2tf32(v.z));
            Bs[b_r][c + 3] = __uint_as_float(f2tf32(v.w));
        }
        __syncthreads();
#pragma unroll
        for (int ks = 0; ks < 4; ks++) {
            int kk = ks * 8;
            unsigned a[2][4];
#pragma unroll
            for (int mi = 0; mi < 2; mi++) {
                int rb = wm * 32 + mi * 16 + g;
                a[mi][0] = __float_as_uint(As[rb][kk + tg]);
                a[mi][1] = __float_as_uint(As[rb + 8][kk + tg]);
                a[mi][2] = __float_as_uint(As[rb][kk + tg + 4]);
                a[mi][3] = __float_as_uint(As[rb + 8][kk + tg + 4]);
            }
#pragma unroll
            for (int nt = 0; nt < 8; nt++) {
                int col = wn * 64 + nt * 8 + g;
                unsigned b0 = __float_as_uint(Bs[kk + tg][col]);
                unsigned b1 = __float_as_uint(Bs[kk + tg + 4][col]);
                mma_tf32(acc[0][nt], a[0], b0, b1);
                mma_tf32(acc[1][nt], a[1], b0, b1);
            }
        }
        __syncthreads();
    }
    // epilogue
#pragma unroll
    for (int mi = 0; mi < 2; mi++) {
        int r = m0 + wm * 32 + mi * 16 + g;
#pragma unroll
        for (int nt = 0; nt < 8; nt++) {
            int c = n0 + wn * 64 + nt * 8 + tg * 2;
            if (r < NN) {
                g_h1[(size_t)r * C1 + c]     = acc[mi][nt][0];
                g_h1[(size_t)r * C1 + c + 1] = acc[mi][nt][1];
            }
            if (r + 8 < NN) {
                g_h1[(size_t)(r + 8) * C1 + c]     = acc[mi][nt][2];
                g_h1[(size_t)(r + 8) * C1 + c + 1] = acc[mi][nt][3];
            }
        }
    }
}

// ---------------- GEMM2: h2 = elu(out1 + b1) @ W2, + fused alpha2 ----------
// block tile 128x40, 8 warps (one 16-row m-tile each), 5 n-tiles of 8.
__global__ __launch_bounds__(256) void gemm2_kernel(const float* __restrict__ W2,
                                                    const float* __restrict__ b1,
                                                    const float* __restrict__ a2s,
                                                    const float* __restrict__ a2d) {
    __shared__ float As[128][36];
    __shared__ float Bs[32][44];
    int tid = threadIdx.x;
    int lane = tid & 31, wid = tid >> 5;
    int g = lane >> 2, tg = lane & 3;
    int m0 = blockIdx.x * 128;

    float acc[5][4];
#pragma unroll
    for (int j = 0; j < 5; j++)
#pragma unroll
        for (int k = 0; k < 4; k++) acc[j][k] = 0.f;

    int a_r = tid >> 3;
    int a_c = (tid & 7) * 4;

    for (int k0 = 0; k0 < C1; k0 += 32) {
        float4 bb = *reinterpret_cast<const float4*>(&b1[k0 + a_c]);
#pragma unroll
        for (int j = 0; j < 4; j++) {
            int r = a_r + 32 * j;
            int gm = m0 + r;
            float4 v = make_float4(0.f, 0.f, 0.f, 0.f);
            if (gm < NN) {
                v = *reinterpret_cast<const float4*>(&g_out1[(size_t)gm * C1 + k0 + a_c]);
                v.x += bb.x; v.y += bb.y; v.z += bb.z; v.w += bb.w;
                v.x = v.x > 0.f ? v.x : expm1f(v.x);
                v.y = v.y > 0.f ? v.y : expm1f(v.y);
                v.z = v.z > 0.f ? v.z : expm1f(v.z);
                v.w = v.w > 0.f ? v.w : expm1f(v.w);
            }
            As[r][a_c + 0] = __uint_as_float(f2tf32(v.x));
            As[r][a_c + 1] = __uint_as_float(f2tf32(v.y));
            As[r][a_c + 2] = __uint_as_float(f2tf32(v.z));
            As[r][a_c + 3] = __uint_as_float(f2tf32(v.w));
        }
        for (int idx = tid; idx < 32 * OUTC; idx += 256) {
            int r = idx / OUTC, c = idx % OUTC;
            Bs[r][c] = __uint_as_float(f2tf32(W2[(size_t)(k0 + r) * OUTC + c]));
        }
        __syncthreads();
#pragma unroll
        for (int ks = 0; ks < 4; ks++) {
            int kk = ks * 8;
            unsigned a[4];
            int rb = wid * 16 + g;
            a[0] = __float_as_uint(As[rb][kk + tg]);
            a[1] = __float_as_uint(As[rb + 8][kk + tg]);
            a[2] = __float_as_uint(As[rb][kk + tg + 4]);
            a[3] = __float_as_uint(As[rb + 8][kk + tg + 4]);
#pragma unroll
            for (int nt = 0; nt < 5; nt++) {
                int col = nt * 8 + g;
                unsigned b0 = __float_as_uint(Bs[kk + tg][col]);
                unsigned b1r = __float_as_uint(Bs[kk + tg + 4][col]);
                mma_tf32(acc[nt], a, b0, b1r);
            }
        }
        __syncthreads();
    }
    // epilogue: store h2 + fused alpha2 (per-row dot with a2s/a2d)
    int rlo = m0 + wid * 16 + g;
    int rhi = rlo + 8;
    float s_lo = 0.f, s_hi = 0.f, d_lo = 0.f, d_hi = 0.f;
#pragma unroll
    for (int nt = 0; nt < 5; nt++) {
        int c = nt * 8 + tg * 2;
        float w0s = a2s[c], w1s = a2s[c + 1];
        float w0d = a2d[c], w1d = a2d[c + 1];
        if (rlo < NN) {
            g_h2[(size_t)rlo * OUTC + c]     = acc[nt][0];
            g_h2[(size_t)rlo * OUTC + c + 1] = acc[nt][1];
        }
        if (rhi < NN) {
            g_h2[(size_t)rhi * OUTC + c]     = acc[nt][2];
            g_h2[(size_t)rhi * OUTC + c + 1] = acc[nt][3];
        }
        s_lo += acc[nt][0] * w0s + acc[nt][1] * w1s;
        s_hi += acc[nt][2] * w0s + acc[nt][3] * w1s;
        d_lo += acc[nt][0] * w0d + acc[nt][1] * w1d;
        d_hi += acc[nt][2] * w0d + acc[nt][3] * w1d;
    }
#pragma unroll
    for (int o = 1; o <= 2; o <<= 1) {
        s_lo += __shfl_xor_sync(~0u, s_lo, o);
        s_hi += __shfl_xor_sync(~0u, s_hi, o);
        d_lo += __shfl_xor_sync(~0u, d_lo, o);
        d_hi += __shfl_xor_sync(~0u, d_hi, o);
    }
    if (tg == 0) {
        if (rlo < NN) { g_as2[rlo] = s_lo; g_ad2[rlo] = d_lo; }
        if (rhi < NN) { g_as2[rhi] = s_hi; g_ad2[rhi] = d_hi; }
    }
}

// ---------------- alpha projections (layer 1) --------------------------------
__global__ void alpha1_kernel(const float* __restrict__ a_src, const float* __restrict__ a_dst) {
    int n = blockIdx.x;
    int t = threadIdx.x;
    int h = t >> 5, l = t & 31;
    float v = g_h1[n * C1 + t];
    float s = v * a_src[t];
    float d = v * a_dst[t];
#pragma unroll
    for (int o = 16; o; o >>= 1) {
        s += __shfl_xor_sync(~0u, s, o);
        d += __shfl_xor_sync(~0u, d, o);
    }
    if (l == 0) { g_as1[n * HEADS + h] = s; g_ad1[n * HEADS + h] = d; }
}

// ---------------- layer1 edge passes (no max pass; logits are tiny) ---------
__global__ void edge_exp1(const int* __restrict__ ei) {
    int i = blockIdx.x * blockDim.x + threadIdx.x;
    if (i >= ET * HEADS) return;
    int e = i >> 3, h = i & 7;
    int s, d;
    if (e < E0) { s = ei[e]; d = ei[E0 + e]; } else { s = d = e - E0; }
    float v = g_as1[s * HEADS + h] + g_ad1[d * HEADS + h];
    v = v > 0.f ? v : NEG * v;
    float ex = __expf(v);
    g_e1[i] = ex;
    atomicAdd(&g_den1[d * HEADS + h], ex);
}

// warp per edge; two iterations of 32 lanes x float4 cover 256 channels
__global__ void edge_aggr1(const int* __restrict__ ei) {
    int w = (blockIdx.x * blockDim.x + threadIdx.x) >> 5;
    int l = threadIdx.x & 31;
    if (w >= ET) return;
    int s, d;
    if (w < E0) { s = ei[w]; d = ei[E0 + w]; } else { s = d = w - E0; }
#pragma unroll
    for (int p = 0; p < 2; p++) {
        int ch = p * 128 + l * 4;
        int h = ch >> 5;
        float ex  = g_e1[w * HEADS + h];
        float den = g_den1[d * HEADS + h];
        float al  = ex / (den + 1e-16f);
        float4 hv = *reinterpret_cast<const float4*>(&g_h1[s * C1 + ch]);
        red_add_v4(&g_out1[d * C1 + ch], hv.x * al, hv.y * al, hv.z * al, hv.w * al);
    }
}

// ---------------- layer2 edge passes -----------------------------------------
__global__ void edge_exp2(const int* __restrict__ ei) {
    int e = blockIdx.x * blockDim.x + threadIdx.x;
    if (e >= ET) return;
    int s, d;
    if (e < E0) { s = ei[e]; d = ei[E0 + e]; } else { s = d = e - E0; }
    float v = g_as2[s] + g_ad2[d];
    v = v > 0.f ? v : NEG * v;
    float ex = __expf(v);
    g_e2[e] = ex;
    atomicAdd(&g_den2[d], ex);
}

// warp per edge; lanes 0..9 handle 40 channels via float4
__global__ void edge_aggr2(const int* __restrict__ ei) {
    int w = (blockIdx.x * blockDim.x + threadIdx.x) >> 5;
    int l = threadIdx.x & 31;
    if (w >= ET) return;
    int s, d;
    if (w < E0) { s = ei[w]; d = ei[E0 + w]; } else { s = d = w - E0; }
    if (l < OUTC / 4) {
        float al = g_e2[w] / (g_den2[d] + 1e-16f);
        float4 hv = *reinterpret_cast<const float4*>(&g_h2[s * OUTC + l * 4]);
        red_add_v4(&g_out2[d * OUTC + l * 4], hv.x * al, hv.y * al, hv.z * al, hv.w * al);
    }
}

// ---------------- log_softmax -------------------------------------------------
__global__ void lsm_kernel(const float* __restrict__ b2, float* __restrict__ out) {
    int w = (blockIdx.x * blockDim.x + threadIdx.x) >> 5;
    int l = threadIdx.x & 31;
    if (w >= NN) return;
    float v1 = g_out2[w * OUTC + l] + b2[l];
    float v2 = (l < 8) ? (g_out2[w * OUTC + 32 + l] + b2[32 + l]) : -1e30f;
    float m = fmaxf(v1, v2);
#pragma unroll
    for (int o = 16; o; o >>= 1) m = fmaxf(m, __shfl_xor_sync(~0u, m, o));
    float sum = __expf(v1 - m) + ((l < 8) ? __expf(v2 - m) : 0.f);
#pragma unroll
    for (int o = 16; o; o >>= 1) sum += __shfl_xor_sync(~0u, sum, o);
    float lse = m + logf(sum);
    out[w * OUTC + l] = v1 - lse;
    if (l < 8) out[w * OUTC + 32 + l] = v2 - lse;
}

// ---------------- launch --------------------------------------------------------
extern "C" void kernel_launch(void* const* d_in, const int* in_sizes, int n_in,
                              void* d_out, int out_size) {
    const float* x   = (const float*)d_in[0];
    const int*   ei  = (const int*)d_in[1];
    const float* W1  = (const float*)d_in[2];
    const float* a1s = (const float*)d_in[3];
    const float* a1d = (const float*)d_in[4];
    const float* b1  = (const float*)d_in[5];
    const float* W2  = (const float*)d_in[6];
    const float* a2s = (const float*)d_in[7];
    const float* a2d = (const float*)d_in[8];
    const float* b2  = (const float*)d_in[9];
    float*       out = (float*)d_out;

    init_kernel<<<2048, 256>>>();

    gemm1_kernel<<<dim3(2, (NN + 127) / 128), 256>>>(x, W1);
    alpha1_kernel<<<NN, 256>>>(a1s, a1d);

    edge_exp1<<<(ET * HEADS + 255) / 256, 256>>>(ei);
    edge_aggr1<<<(ET + 7) / 8, 256>>>(ei);

    gemm2_kernel<<<(NN + 127) / 128, 256>>>(W2, b1, a2s, a2d);

    edge_exp2<<<(ET + 255) / 256, 256>>>(ei);
    edge_aggr2<<<(ET + 7) / 8, 256>>>(ei);

    lsm_kernel<<<(NN + 7) / 8, 256>>>(b2, out);
}